// round 17
// baseline (speedup 1.0000x reference)
#include <cuda_runtime.h>
#include <cuda_fp16.h>
#include <math.h>

#define B_ 8
#define T_ 2048
#define C_ 1024
#define H_ 64
#define NROWS (B_ * T_)   // 16384

__device__ float g_q[NROWS * H_];
__device__ float g_k[NROWS * H_];
__device__ float g_v[NROWS * H_];
__device__ float g_res[NROWS * H_];
__device__ float g_rowsum[NROWS];
__device__ __half g_e[(size_t)B_ * T_ * T_];        // fp16 unnormalized E
__device__ float g_attn_scratch[(size_t)B_ * T_ * T_];

// ---- fp16 helpers -----------------------------------------------------------
__device__ __forceinline__ uint2 pack_h4(float4 f) {
    __half2 h0 = __floats2half2_rn(f.x, f.y);
    __half2 h1 = __floats2half2_rn(f.z, f.w);
    uint2 u;
    u.x = *(unsigned*)&h0;
    u.y = *(unsigned*)&h1;
    return u;
}
// D += A(16x16,row) * B(16x8,col); fp16 in, fp32 accum
__device__ __forceinline__ void mma16(float* c, const unsigned* a, const unsigned* b) {
    asm("mma.sync.aligned.m16n8k16.row.col.f32.f16.f16.f32 "
        "{%0,%1,%2,%3},{%4,%5,%6,%7},{%8,%9},{%0,%1,%2,%3};"
        : "+f"(c[0]), "+f"(c[1]), "+f"(c[2]), "+f"(c[3])
        : "r"(a[0]), "r"(a[1]), "r"(a[2]), "r"(a[3]), "r"(b[0]), "r"(b[1]));
}
__device__ __forceinline__ void ldmA16(unsigned* a, unsigned saddr) {
    asm volatile("ldmatrix.sync.aligned.m8n8.x4.shared.b16 {%0,%1,%2,%3}, [%4];"
        : "=r"(a[0]), "=r"(a[1]), "=r"(a[2]), "=r"(a[3]) : "r"(saddr));
}
__device__ __forceinline__ void ldmBT(unsigned* b, unsigned saddr) {
    asm volatile("ldmatrix.sync.aligned.m8n8.x2.trans.shared.b16 {%0,%1}, [%2];"
        : "=r"(b[0]), "=r"(b[1]) : "r"(saddr));
}

// ---------------------------------------------------------------------------
// Kernel 1: QKV projection, fp16 MMA, K-chunk 128 (8 k16 steps, 8 chunks).
// grid=(128, 3), block=128 (2m x 2n warps). Block tile 128m x 64h.
// Warp tile 64m x 32h. smem: Xh[128][136] + Wh[128][72] = 53248 B.
// ---------------------------------------------------------------------------
#define XP 136
#define PROJ_SMEM (128 * XP * 2 + 128 * 72 * 2)
__global__ __launch_bounds__(128) void proj_kernel(const float* __restrict__ x,
                                                   const float* __restrict__ Wq,
                                                   const float* __restrict__ Wk,
                                                   const float* __restrict__ Wv) {
    extern __shared__ __half smh[];
    __half* Xh = smh;              // [128][136]
    __half* Wh = smh + 128 * XP;   // [128][72]

    const float* W; float* out;
    if (blockIdx.y == 0)      { W = Wq; out = g_q; }
    else if (blockIdx.y == 1) { W = Wk; out = g_k; }
    else                      { W = Wv; out = g_v; }

    const int row0 = blockIdx.x * 128;
    const int tid  = threadIdx.x;
    const int warp = tid >> 5;
    const int lane = tid & 31;
    const int g    = lane >> 2;
    const int tig  = lane & 3;
    const int wm   = warp >> 1;
    const int wn   = warp & 1;

    const unsigned xh_base = (unsigned)__cvta_generic_to_shared(Xh);
    const unsigned wh_base = (unsigned)__cvta_generic_to_shared(Wh);
    const int l16   = lane & 15;
    const int koff8 = (lane >> 4) * 8;

    float acc[4][4][4] = {};

    for (int k0 = 0; k0 < C_; k0 += 128) {
        #pragma unroll
        for (int it = 0; it < 32; it++) {
            int idx = tid + it * 128;          // 4096 float4 = 128 x 32
            int r = idx >> 5, c4 = idx & 31;
            *(uint2*)&Xh[r * XP + c4 * 4] =
                pack_h4(*(const float4*)&x[(size_t)(row0 + r) * C_ + k0 + c4 * 4]);
        }
        #pragma unroll
        for (int it = 0; it < 16; it++) {
            int idx = tid + it * 128;          // 2048 float4 = 128 x 16
            int r = idx >> 4, c4 = idx & 15;
            *(uint2*)&Wh[r * 72 + c4 * 4] =
                pack_h4(*(const float4*)&W[(size_t)(k0 + r) * H_ + c4 * 4]);
        }
        __syncthreads();

        #pragma unroll
        for (int k16 = 0; k16 < 8; k16++) {
            const int kb = k16 * 16;
            unsigned a[4][4];
            #pragma unroll
            for (int mi = 0; mi < 4; mi++) {
                int m0 = wm * 64 + mi * 16;
                ldmA16(a[mi], xh_base + (((m0 + l16) * XP + kb + koff8) << 1));
            }
            #pragma unroll
            for (int nj = 0; nj < 4; nj++) {
                int n0 = wn * 32 + nj * 8;
                unsigned b[2];
                ldmBT(b, wh_base + (((kb + l16) * 72 + n0) << 1));
                #pragma unroll
                for (int mi = 0; mi < 4; mi++) mma16(acc[mi][nj], a[mi], b);
            }
        }
        __syncthreads();
    }

    #pragma unroll
    for (int mi = 0; mi < 4; mi++) {
        #pragma unroll
        for (int nj = 0; nj < 4; nj++) {
            int m0 = row0 + wm * 64 + mi * 16;
            int n0 = wn * 32 + nj * 8 + tig * 2;
            float* c = acc[mi][nj];
            *(float2*)&out[(size_t)(m0 + g) * H_ + n0]     = make_float2(c[0], c[1]);
            *(float2*)&out[(size_t)(m0 + g + 8) * H_ + n0] = make_float2(c[2], c[3]);
        }
    }
}

// ---------------------------------------------------------------------------
// Kernel 2: E = exp(Q@K^T / 32), fp16 MMA. Lower tiles -> g_e fp16 + rowsum;
// upper tiles -> zero-fill fp32 attn. grid=(16 s,32 t,8 b), block=128.
// Tile 64t x 128s. (unchanged, known-good)
// ---------------------------------------------------------------------------
#define SCORES_SMEM (64 * 72 * 2 + 128 * 72 * 2)
__global__ __launch_bounds__(128, 4) void scores_kernel(float* __restrict__ attn) {
    const int s_t = blockIdx.x, t_t = blockIdx.y;
    const int b = blockIdx.z;
    const int t0 = t_t * 64, s0 = s_t * 128;
    const int tid = threadIdx.x;

    if (s0 > t0 + 63) {  // strictly-upper tile: zero fill final attn
        #pragma unroll
        for (int it = 0; it < 16; it++) {
            int idx = tid + it * 128;
            int r = idx >> 5, c4 = idx & 31;
            *(float4*)&attn[((size_t)b * T_ + t0 + r) * T_ + s0 + c4 * 4] =
                make_float4(0.f, 0.f, 0.f, 0.f);
        }
        return;
    }

    extern __shared__ __half smh[];
    __half* Qh = smh;            // [64][72]
    __half* Kh = smh + 64 * 72;  // [128][72]

    const float* q = g_q + (size_t)b * T_ * H_;
    const float* k = g_k + (size_t)b * T_ * H_;

    #pragma unroll
    for (int it = 0; it < 8; it++) {
        int idx = tid + it * 128;
        int r = idx >> 4, c4 = idx & 15;
        *(uint2*)&Qh[r * 72 + c4 * 4] =
            pack_h4(*(const float4*)&q[(size_t)(t0 + r) * H_ + c4 * 4]);
    }
    #pragma unroll
    for (int it = 0; it < 16; it++) {
        int idx = tid + it * 128;
        int r = idx >> 4, c4 = idx & 15;
        *(uint2*)&Kh[r * 72 + c4 * 4] =
            pack_h4(*(const float4*)&k[(size_t)(s0 + r) * H_ + c4 * 4]);
    }
    __syncthreads();

    const int warp = tid >> 5;
    const int lane = tid & 31;
    const int g    = lane >> 2;
    const int tig  = lane & 3;
    const unsigned qh_base = (unsigned)__cvta_generic_to_shared(Qh);
    const int l16   = lane & 15;
    const int koff8 = (lane >> 4) * 8;

    float acc[4][4][4] = {};
    #pragma unroll
    for (int k16 = 0; k16 < 4; k16++) {
        const int kb = k16 * 16;
        unsigned a[4][4];
        #pragma unroll
        for (int mi = 0; mi < 4; mi++) {
            ldmA16(a[mi], qh_base + (((mi * 16 + l16) * 72 + kb + koff8) << 1));
        }
        #pragma unroll
        for (int nj = 0; nj < 4; nj++) {
            int n0 = warp * 32 + nj * 8;
            unsigned bb[2];
            bb[0] = *(unsigned*)&Kh[(n0 + g) * 72 + kb + tig * 2];
            bb[1] = *(unsigned*)&Kh[(n0 + g) * 72 + kb + tig * 2 + 8];
            #pragma unroll
            for (int mi = 0; mi < 4; mi++) mma16(acc[mi][nj], a[mi], bb);
        }
    }

    const float sc = 0.03125f;  // 1/sqrt(1024)
    const bool need_mask = (s0 + 127 > t0);
    #pragma unroll
    for (int mi = 0; mi < 4; mi++) {
        const int trow0 = t0 + mi * 16 + g;
        const int trow1 = trow0 + 8;
        const size_t row0g = (size_t)b * T_ + trow0;
        const size_t row1g = (size_t)b * T_ + trow1;
        float rs0 = 0.f, rs1 = 0.f;
        #pragma unroll
        for (int nj = 0; nj < 4; nj++) {
            int col = s0 + warp * 32 + nj * 8 + tig * 2;
            float* c = acc[mi][nj];
            float e0 = (!need_mask || col     <= trow0) ? __expf(c[0] * sc) : 0.f;
            float e1 = (!need_mask || col + 1 <= trow0) ? __expf(c[1] * sc) : 0.f;
            float e2 = (!need_mask || col     <= trow1) ? __expf(c[2] * sc) : 0.f;
            float e3 = (!need_mask || col + 1 <= trow1) ? __expf(c[3] * sc) : 0.f;
            rs0 += e0 + e1; rs1 += e2 + e3;
            *(__half2*)&g_e[row0g * T_ + col] = __floats2half2_rn(e0, e1);
            *(__half2*)&g_e[row1g * T_ + col] = __floats2half2_rn(e2, e3);
        }
        rs0 += __shfl_xor_sync(0xffffffffu, rs0, 1);
        rs0 += __shfl_xor_sync(0xffffffffu, rs0, 2);
        rs1 += __shfl_xor_sync(0xffffffffu, rs1, 1);
        rs1 += __shfl_xor_sync(0xffffffffu, rs1, 2);
        if (tig == 0) {
            atomicAdd(&g_rowsum[row0g], rs0);
            atomicAdd(&g_rowsum[row1g], rs1);
        }
    }
}

// ---------------------------------------------------------------------------
// Kernel 3: res += (E/rowsum) @ V, fp16 MMA, split-K over 256-wide s-spans,
// inner s-chunk 128 (8 k16 steps, <=2 chunks). grid=(8 spans, 32 t desc, 8 b),
// block=128 (4 warps 2x2). Tile 64t x 64h.
// smem: As[64][136] + Vh[128][72] + sinv = 36096 B.
// ---------------------------------------------------------------------------
#define AP 136
#define AV_SMEM (64 * AP * 2 + 128 * 72 * 2 + 64 * 4)
__global__ __launch_bounds__(128, 4) void av_kernel(float* __restrict__ attn,
                                                    float* __restrict__ res) {
    const int sc   = blockIdx.x;
    const int t_t  = 31 - blockIdx.y;   // big tiles first
    const int b    = blockIdx.z;
    const int t0   = t_t * 64;
    if (sc * 256 > t0 + 63) return;

    extern __shared__ __half smh[];
    __half* As = smh;             // [64][136]
    __half* Vh = smh + 64 * AP;   // [128][72]
    float* sinv = (float*)(smh + 64 * AP + 128 * 72);

    const int tid = threadIdx.x;
    if (tid < 64) sinv[tid] = 1.f / g_rowsum[(size_t)b * T_ + t0 + tid];
    __syncthreads();

    const float* v = g_v + (size_t)b * T_ * H_;
    const int warp = tid >> 5;
    const int lane = tid & 31;
    const int g    = lane >> 2;
    const int tig  = lane & 3;
    const int wm   = warp >> 1;
    const int wn   = warp & 1;
    const unsigned as_base = (unsigned)__cvta_generic_to_shared(As);
    const unsigned vh_base = (unsigned)__cvta_generic_to_shared(Vh);
    const int l16   = lane & 15;
    const int koff8 = (lane >> 4) * 8;

    float acc[2][4][4] = {};

    #pragma unroll
    for (int c2 = 0; c2 < 2; c2++) {
        const int s0 = sc * 256 + c2 * 128;
        if (s0 > t0 + 63) break;

        // E loader: 64 rows x 128 s = 8192 halves; 1024 uint4 -> 8 iters
        #pragma unroll
        for (int it = 0; it < 8; it++) {
            int idx = tid + it * 128;
            int r = idx >> 4, c8 = idx & 15;
            size_t rowg = (size_t)b * T_ + t0 + r;
            uint4 raw = *(const uint4*)&g_e[rowg * T_ + s0 + c8 * 8];
            float iv = sinv[r];
            float2 f0 = __half22float2(*(__half2*)&raw.x);
            float2 f1 = __half22float2(*(__half2*)&raw.y);
            float2 f2 = __half22float2(*(__half2*)&raw.z);
            float2 f3 = __half22float2(*(__half2*)&raw.w);
            float4 a0 = make_float4(f0.x * iv, f0.y * iv, f1.x * iv, f1.y * iv);
            float4 a1 = make_float4(f2.x * iv, f2.y * iv, f3.x * iv, f3.y * iv);
            float* ap = &attn[rowg * T_ + s0 + c8 * 8];
            *(float4*)ap       = a0;           // final normalized fp32 attn
            *(float4*)(ap + 4) = a1;
            uint2 p0 = pack_h4(a0);
            uint2 p1 = pack_h4(a1);
            *(uint4*)&As[r * AP + c8 * 8] = make_uint4(p0.x, p0.y, p1.x, p1.y);
        }
        #pragma unroll
        for (int it = 0; it < 16; it++) {
            int idx = tid + it * 128;          // 2048 float4 = 128 x 16
            int r = idx >> 4, c4 = idx & 15;
            *(uint2*)&Vh[r * 72 + c4 * 4] =
                pack_h4(*(const float4*)&v[(size_t)(s0 + r) * H_ + c4 * 4]);
        }
        __syncthreads();

        #pragma unroll
        for (int k16 = 0; k16 < 8; k16++) {
            const int kb = k16 * 16;
            unsigned a[2][4];
            #pragma unroll
            for (int mi = 0; mi < 2; mi++) {
                int m0 = wm * 32 + mi * 16;
                ldmA16(a[mi], as_base + (((m0 + l16) * AP + kb + koff8) << 1));
            }
            #pragma unroll
            for (int nj = 0; nj < 4; nj++) {
                int n0 = wn * 32 + nj * 8;
                unsigned bb[2];
                ldmBT(bb, vh_base + (((kb + l16) * 72 + n0) << 1));
                #pragma unroll
                for (int mi = 0; mi < 2; mi++) mma16(acc[mi][nj], a[mi], bb);
            }
        }
        __syncthreads();
    }

    #pragma unroll
    for (int mi = 0; mi < 2; mi++) {
        #pragma unroll
        for (int nj = 0; nj < 4; nj++) {
            int m0 = t0 + wm * 32 + mi * 16;
            int n0 = wn * 32 + nj * 8 + tig * 2;
            float* c = acc[mi][nj];
            size_t r0 = ((size_t)b * T_ + m0 + g) * H_ + n0;
            size_t r1 = ((size_t)b * T_ + m0 + g + 8) * H_ + n0;
            atomicAdd(&res[r0],     c[0]);
            atomicAdd(&res[r0 + 1], c[1]);
            atomicAdd(&res[r1],     c[2]);
            atomicAdd(&res[r1 + 1], c[3]);
        }
    }
}

// ---------------------------------------------------------------------------
extern "C" void kernel_launch(void* const* d_in, const int* in_sizes, int n_in,
                              void* d_out, int out_size) {
    (void)in_sizes; (void)n_in;
    const float* x  = (const float*)d_in[0];
    const float* Wq = (const float*)d_in[1];
    const float* Wk = (const float*)d_in[2];
    const float* Wv = (const float*)d_in[3];

    const size_t n_res  = (size_t)B_ * T_ * H_;
    const size_t n_attn = (size_t)B_ * T_ * T_;

    float* attn_scratch = nullptr;
    float* res_scratch = nullptr;
    float* rowsum = nullptr;
    cudaGetSymbolAddress((void**)&attn_scratch, g_attn_scratch);
    cudaGetSymbolAddress((void**)&res_scratch, g_res);
    cudaGetSymbolAddress((void**)&rowsum, g_rowsum);

    float* res;
    float* attn;
    if ((size_t)out_size == n_res + n_attn) {
        res  = (float*)d_out;
        attn = (float*)d_out + n_res;
    } else if ((size_t)out_size == n_attn) {
        attn = (float*)d_out;
        res  = res_scratch;
    } else {
        res  = (float*)d_out;
        attn = attn_scratch;
    }

    cudaFuncSetAttribute(proj_kernel,   cudaFuncAttributeMaxDynamicSharedMemorySize, PROJ_SMEM);
    cudaFuncSetAttribute(scores_kernel, cudaFuncAttributeMaxDynamicSharedMemorySize, SCORES_SMEM);
    cudaFuncSetAttribute(av_kernel,     cudaFuncAttributeMaxDynamicSharedMemorySize, AV_SMEM);

    cudaMemsetAsync(rowsum, 0, NROWS * sizeof(float));
    cudaMemsetAsync(res, 0, n_res * sizeof(float));
    proj_kernel<<<dim3(128, 3), 128, PROJ_SMEM>>>(x, Wq, Wk, Wv);
    scores_kernel<<<dim3(16, 32, 8), 128, SCORES_SMEM>>>(attn);
    av_kernel<<<dim3(8, 32, 8), 128, AV_SMEM>>>(attn, res);
}